// round 12
// baseline (speedup 1.0000x reference)
#include <cuda_runtime.h>
#include <math.h>

#define BB    16
#define MMM   1024
#define NN    512
#define CC    8
#define COUT  64
#define NSLC  4               // cluster size = n-slices per (b, mtile) group
#define NSL   (NN / NSLC)     // 128 n per CTA
#define NWARP 8
#define NPW   (NSL / NWARP)   // 16 n per warp
#define MPB   64              // m per group (2 per lane in loop)
#define MEPI  (MPB / NSLC)    // 16 m per CTA in epilogue
#define TPB   (32 * NWARP)    // 256 threads

__device__ __forceinline__ float ex2f(float x) {
    float y;
    asm("ex2.approx.ftz.f32 %0, %1;" : "=f"(y) : "f"(x));
    return y;
}
__device__ __forceinline__ unsigned long long pack2(float lo, float hi) {
    unsigned long long r;
    asm("mov.b64 %0, {%1, %2};" : "=l"(r) : "f"(lo), "f"(hi));
    return r;
}
__device__ __forceinline__ void unpack2(unsigned long long v, float& lo, float& hi) {
    asm("mov.b64 {%0, %1}, %2;" : "=f"(lo), "=f"(hi) : "l"(v));
}
__device__ __forceinline__ void ffma2(unsigned long long& d, unsigned long long a, unsigned long long b) {
    asm("fma.rn.f32x2 %0, %1, %2, %0;" : "+l"(d) : "l"(a), "l"(b));
}
__device__ __forceinline__ unsigned smem_u32(const void* p) {
    unsigned a;
    asm("{ .reg .u64 t; cvta.to.shared.u64 t, %1; cvt.u32.u64 %0, t; }" : "=r"(a) : "l"(p));
    return a;
}
__device__ __forceinline__ void st_cluster_f32(unsigned local_addr, unsigned rank, float v) {
    unsigned remote;
    asm volatile("mapa.shared::cluster.u32 %0, %1, %2;" : "=r"(remote) : "r"(local_addr), "r"(rank));
    asm volatile("st.shared::cluster.f32 [%0], %1;" :: "r"(remote), "f"(v) : "memory");
}

__global__ __launch_bounds__(TPB) __cluster_dims__(NSLC, 1, 1)
void convdeepset_kernel(const float* __restrict__ ci,    // (B,N,1)
                        const float* __restrict__ co,    // (B,N,7)
                        const float* __restrict__ ti,    // (B,M,1)
                        const float* __restrict__ sigma, // (8,)
                        const float* __restrict__ W,     // (64,8)
                        const float* __restrict__ bias,  // (64,)
                        float* __restrict__ out)         // (B,M,64)
{
    __shared__ float4      s_ab2[NSL / 2];            // 1KB
    __shared__ ulonglong2  s_cx[NSL * 2];             // 4KB
    __shared__ float       s_part[NWARP][CC][MPB];    // 16KB
    __shared__ float       s_red[NSLC][CC][MEPI];     // 2KB: partials gathered from peers
    __shared__ float       s_v[CC][MEPI];
    __shared__ float       s_dens[MEPI];
    __shared__ float       s_Wt[CC][COUT];
    __shared__ float       s_bias[COUT];

    const int tid  = threadIdx.x;
    const int w    = tid >> 5;
    const int lane = tid & 31;
    const int blk  = blockIdx.x;
    unsigned rank;
    asm("mov.u32 %0, %%cluster_ctarank;" : "=r"(rank));   // n-slice index 0..3
    const int grp  = blk >> 2;           // 0..255 (b, mtile)
    const int mt   = grp & 15;
    const int b    = grp >> 4;
    const int mbase  = mt * MPB;
    const int nsbase = rank * NSL;

    // stage W^T + bias (all CTAs need them)
    for (int i = tid; i < CC * COUT; i += TPB) {
        int o = i / CC, c = i % CC;
        s_Wt[c][o] = W[i];
    }
    if (tid < COUT) s_bias[tid] = bias[tid];

    // uniform-sigma detection
    const float LOG2E = 1.4426950408889634f;
    float sg0 = sigma[0];
    bool uni = true;
    #pragma unroll
    for (int c = 1; c < CC; c++) uni &= (sigma[c] == sg0);
    const float k2u = -0.5f * LOG2E * expf(-2.0f * sg0);

    // stage this slice's 128 context rows
    const float* cib = ci + (size_t)b * NN + nsbase;
    const float* cob = co + ((size_t)b * NN + nsbase) * 7;
    float2* s_abf2 = (float2*)s_ab2;
    if (tid < NSL) {
        int i = tid;
        float x = cib[i];
        float2 ab;
        if (uni) { ab.x = k2u * x * x; ab.y = -2.0f * k2u * x; }
        else     { ab.x = x;           ab.y = 0.0f; }
        s_abf2[i] = ab;
        const float* r = cob + i * 7;
        s_cx[2 * i]     = make_ulonglong2(pack2(1.0f, r[0]), pack2(r[1], r[2]));
        s_cx[2 * i + 1] = make_ulonglong2(pack2(r[3], r[4]), pack2(r[5], r[6]));
    }
    __syncthreads();

    const float t0 = ti[(size_t)b * MMM + mbase + lane];
    const float t1 = ti[(size_t)b * MMM + mbase + lane + 32];

    const int l0 = w * NPW;
    float f0[CC], f1[CC];

    if (uni) {
        unsigned long long x0 = 0ull, x1 = 0ull, x2 = 0ull, x3 = 0ull;
        unsigned long long y0 = 0ull, y1 = 0ull, y2 = 0ull, y3 = 0ull;
        #pragma unroll
        for (int i = 0; i < NPW / 2; i++) {
            const int np = (l0 >> 1) + i;
            const int n  = l0 + 2 * i;
            float4 ab = s_ab2[np];
            float wa0 = ex2f(fmaf(ab.y, t0, ab.x));
            float wb0 = ex2f(fmaf(ab.w, t0, ab.z));
            float wa1 = ex2f(fmaf(ab.y, t1, ab.x));
            float wb1 = ex2f(fmaf(ab.w, t1, ab.z));
            ulonglong2 pa = s_cx[2 * n];
            ulonglong2 qa = s_cx[2 * n + 1];
            ulonglong2 pb = s_cx[2 * n + 2];
            ulonglong2 qb = s_cx[2 * n + 3];
            unsigned long long wa0p = pack2(wa0, wa0);
            unsigned long long wb0p = pack2(wb0, wb0);
            unsigned long long wa1p = pack2(wa1, wa1);
            unsigned long long wb1p = pack2(wb1, wb1);
            ffma2(x0, wa0p, pa.x); ffma2(x1, wa0p, pa.y);
            ffma2(x2, wa0p, qa.x); ffma2(x3, wa0p, qa.y);
            ffma2(x0, wb0p, pb.x); ffma2(x1, wb0p, pb.y);
            ffma2(x2, wb0p, qb.x); ffma2(x3, wb0p, qb.y);
            ffma2(y0, wa1p, pa.x); ffma2(y1, wa1p, pa.y);
            ffma2(y2, wa1p, qa.x); ffma2(y3, wa1p, qa.y);
            ffma2(y0, wb1p, pb.x); ffma2(y1, wb1p, pb.y);
            ffma2(y2, wb1p, qb.x); ffma2(y3, wb1p, qb.y);
        }
        unpack2(x0, f0[0], f0[1]); unpack2(x1, f0[2], f0[3]);
        unpack2(x2, f0[4], f0[5]); unpack2(x3, f0[6], f0[7]);
        unpack2(y0, f1[0], f1[1]); unpack2(y1, f1[2], f1[3]);
        unpack2(y2, f1[4], f1[5]); unpack2(y3, f1[6], f1[7]);
    } else {
        float k2[CC];
        #pragma unroll
        for (int c = 0; c < CC; c++) k2[c] = -0.5f * LOG2E * expf(-2.0f * sigma[c]);
        #pragma unroll
        for (int c = 0; c < CC; c++) { f0[c] = 0.0f; f1[c] = 0.0f; }
        for (int i = 0; i < NPW; i++) {
            int n = l0 + i;
            float x = s_abf2[n].x;
            float d0 = (x - t0) * (x - t0);
            float d1 = (x - t1) * (x - t1);
            const float* cf = (const float*)&s_cx[2 * n];
            #pragma unroll
            for (int c = 0; c < CC; c++) {
                f0[c] += ex2f(d0 * k2[c]) * cf[c];
                f1[c] += ex2f(d1 * k2[c]) * cf[c];
            }
        }
    }

    #pragma unroll
    for (int c = 0; c < CC; c++) {
        s_part[w][c][lane]      = f0[c];
        s_part[w][c][lane + 32] = f1[c];
    }
    __syncthreads();

    // in-CTA reduce over 8 warps, then DSMEM-scatter to the m-quarter owners
    {
        const int c   = tid >> 5;       // 0..7
        const int mm0 = tid & 31;       // m local 0..31 (and mm0+32)
        float acc0 = 0.0f, acc1 = 0.0f;
        #pragma unroll
        for (int ww = 0; ww < NWARP; ww++) {
            acc0 += s_part[ww][c][mm0];
            acc1 += s_part[ww][c][mm0 + 32];
        }
        // destination CTA owns m in [16j, 16j+16)
        const unsigned j0 = mm0 >> 4;            // 0..1
        const unsigned j1 = 2 + j0;              // 2..3  (for mm0+32)
        const int mloc = mm0 & 15;
        unsigned base = smem_u32(&s_red[rank][c][mloc]);  // slot indexed by MY slice
        st_cluster_f32(base, j0, acc0);
        st_cluster_f32(base, j1, acc1);
    }

    // make DSMEM stores visible cluster-wide, then barrier
    asm volatile("fence.acq_rel.cluster;" ::: "memory");
    asm volatile("barrier.cluster.arrive.aligned;" ::: "memory");
    asm volatile("barrier.cluster.wait.aligned;" ::: "memory");

    // ---- epilogue: this CTA owns m = mbase + rank*16 + [0,16) ----
    const int mepi_base = mbase + (int)rank * MEPI;

    if (tid < CC * MEPI) {              // 128 threads: c = tid>>4, mloc = tid&15
        const int c    = tid >> 4;
        const int mloc = tid & 15;
        float acc = s_red[0][c][mloc] + s_red[1][c][mloc]
                  + s_red[2][c][mloc] + s_red[3][c][mloc];
        if (c == 0) s_dens[mloc] = acc;
        s_v[c][mloc] = acc;             // raw sums for now
    }
    __syncthreads();
    if (tid < CC * MEPI) {
        const int c    = tid >> 4;
        const int mloc = tid & 15;
        float tm = ti[(size_t)b * MMM + mepi_base + mloc];
        float g  = uni ? ex2f(k2u * tm * tm) : 1.0f;
        float d0 = s_dens[mloc] * g;                 // true density
        float inv = g / (d0 + 1e-8f);
        s_v[c][mloc] = (c == 0) ? d0 : s_v[c][mloc] * inv;
    }
    __syncthreads();

    // (8 -> 64) GEMM + bias: thread = (mloc = tid>>4, og = tid&15), one float4
    {
        const int mloc = tid >> 4;
        const int og   = tid & 15;
        float vv[CC];
        #pragma unroll
        for (int c = 0; c < CC; c++) vv[c] = s_v[c][mloc];

        float4 r = *(const float4*)&s_bias[og * 4];
        #pragma unroll
        for (int c = 0; c < CC; c++) {
            float4 w4 = *(const float4*)&s_Wt[c][og * 4];
            r.x = fmaf(vv[c], w4.x, r.x);
            r.y = fmaf(vv[c], w4.y, r.y);
            r.z = fmaf(vv[c], w4.z, r.z);
            r.w = fmaf(vv[c], w4.w, r.w);
        }
        float4* outp = (float4*)(out + ((size_t)(b * MMM + mepi_base + mloc)) * COUT + og * 4);
        *outp = r;
    }

    // trailing cluster barrier: no CTA exits while peers could still be mid-epilogue
    asm volatile("barrier.cluster.arrive.aligned;" ::: "memory");
    asm volatile("barrier.cluster.wait.aligned;" ::: "memory");
}

extern "C" void kernel_launch(void* const* d_in, const int* in_sizes, int n_in,
                              void* d_out, int out_size) {
    const float* ci    = (const float*)d_in[0];
    const float* co    = (const float*)d_in[1];
    const float* ti    = (const float*)d_in[2];
    const float* sigma = (const float*)d_in[3];
    const float* W     = (const float*)d_in[4];
    const float* bias  = (const float*)d_in[5];
    float* out = (float*)d_out;

    dim3 grid(BB * (MMM / MPB) * NSLC);   // 1024 CTAs = 256 clusters of 4
    dim3 block(TPB);                      // 256 threads
    convdeepset_kernel<<<grid, block>>>(ci, co, ti, sigma, W, bias, out);
}

// round 13
// speedup vs baseline: 1.0625x; 1.0625x over previous
#include <cuda_runtime.h>
#include <math.h>

#define BB    16
#define MMM   1024
#define NN    512
#define CC    8
#define COUT  64
#define NSLC  4               // n-slices (CTAs) per (b, mtile) group
#define NSL   (NN / NSLC)     // 128 n per slice
#define NWARP 8
#define NPW   (NSL / NWARP)   // 16 n per warp
#define MPB   64              // m per group (2 per lane)
#define TPB   (32 * NWARP)    // 256 threads (main)
#define RTPB  512             // threads (reduce)
#define NGRP  (BB * (MMM / MPB))  // 256 groups

__device__ float g_part[NGRP * NSLC * CC * MPB];  // 2MB partials (L2-resident)

__device__ __forceinline__ float ex2f(float x) {
    float y;
    asm("ex2.approx.ftz.f32 %0, %1;" : "=f"(y) : "f"(x));
    return y;
}
__device__ __forceinline__ unsigned long long pack2(float lo, float hi) {
    unsigned long long r;
    asm("mov.b64 %0, {%1, %2};" : "=l"(r) : "f"(lo), "f"(hi));
    return r;
}
__device__ __forceinline__ void unpack2(unsigned long long v, float& lo, float& hi) {
    asm("mov.b64 {%0, %1}, %2;" : "=f"(lo), "=f"(hi) : "l"(v));
}
__device__ __forceinline__ void ffma2(unsigned long long& d, unsigned long long a, unsigned long long b) {
    asm("fma.rn.f32x2 %0, %1, %2, %0;" : "+l"(d) : "l"(a), "l"(b));
}

// ---------------- main kernel: partial sums over one 128-n slice ----------------
__global__ __launch_bounds__(TPB)
void convdeepset_main(const float* __restrict__ ci,    // (B,N,1)
                      const float* __restrict__ co,    // (B,N,7)
                      const float* __restrict__ ti,    // (B,M,1)
                      const float* __restrict__ sigma) // (8,)
{
    __shared__ float4      s_ab2[NSL / 2];           // 1KB
    __shared__ ulonglong2  s_cx[NSL * 2];            // 4KB
    __shared__ float       s_part[NWARP][CC][MPB];   // 16KB

    const int tid  = threadIdx.x;
    const int w    = tid >> 5;
    const int lane = tid & 31;
    const int blk  = blockIdx.x;
    const int ns   = blk & (NSLC - 1);
    const int grp  = blk >> 2;
    const int mt   = grp & 15;
    const int b    = grp >> 4;
    const int mbase  = mt * MPB;
    const int nsbase = ns * NSL;

    const float LOG2E = 1.4426950408889634f;
    float sg0 = sigma[0];
    bool uni = true;
    #pragma unroll
    for (int c = 1; c < CC; c++) uni &= (sigma[c] == sg0);
    const float k2u = -0.5f * LOG2E * expf(-2.0f * sg0);

    const float* cib = ci + (size_t)b * NN + nsbase;
    const float* cob = co + ((size_t)b * NN + nsbase) * 7;
    float2* s_abf2 = (float2*)s_ab2;
    if (tid < NSL) {
        int i = tid;
        float x = cib[i];
        float2 ab;
        if (uni) { ab.x = k2u * x * x; ab.y = -2.0f * k2u * x; }
        else     { ab.x = x;           ab.y = 0.0f; }
        s_abf2[i] = ab;
        const float* r = cob + i * 7;
        s_cx[2 * i]     = make_ulonglong2(pack2(1.0f, r[0]), pack2(r[1], r[2]));
        s_cx[2 * i + 1] = make_ulonglong2(pack2(r[3], r[4]), pack2(r[5], r[6]));
    }
    __syncthreads();

    const float t0 = ti[(size_t)b * MMM + mbase + lane];
    const float t1 = ti[(size_t)b * MMM + mbase + lane + 32];

    const int l0 = w * NPW;
    float f0[CC], f1[CC];

    if (uni) {
        unsigned long long x0 = 0ull, x1 = 0ull, x2 = 0ull, x3 = 0ull;
        unsigned long long y0 = 0ull, y1 = 0ull, y2 = 0ull, y3 = 0ull;
        #pragma unroll
        for (int i = 0; i < NPW / 2; i++) {
            const int np = (l0 >> 1) + i;
            const int n  = l0 + 2 * i;
            float4 ab = s_ab2[np];
            float wa0 = ex2f(fmaf(ab.y, t0, ab.x));
            float wb0 = ex2f(fmaf(ab.w, t0, ab.z));
            float wa1 = ex2f(fmaf(ab.y, t1, ab.x));
            float wb1 = ex2f(fmaf(ab.w, t1, ab.z));
            ulonglong2 pa = s_cx[2 * n];
            ulonglong2 qa = s_cx[2 * n + 1];
            ulonglong2 pb = s_cx[2 * n + 2];
            ulonglong2 qb = s_cx[2 * n + 3];
            unsigned long long wa0p = pack2(wa0, wa0);
            unsigned long long wb0p = pack2(wb0, wb0);
            unsigned long long wa1p = pack2(wa1, wa1);
            unsigned long long wb1p = pack2(wb1, wb1);
            ffma2(x0, wa0p, pa.x); ffma2(x1, wa0p, pa.y);
            ffma2(x2, wa0p, qa.x); ffma2(x3, wa0p, qa.y);
            ffma2(x0, wb0p, pb.x); ffma2(x1, wb0p, pb.y);
            ffma2(x2, wb0p, qb.x); ffma2(x3, wb0p, qb.y);
            ffma2(y0, wa1p, pa.x); ffma2(y1, wa1p, pa.y);
            ffma2(y2, wa1p, qa.x); ffma2(y3, wa1p, qa.y);
            ffma2(y0, wb1p, pb.x); ffma2(y1, wb1p, pb.y);
            ffma2(y2, wb1p, qb.x); ffma2(y3, wb1p, qb.y);
        }
        unpack2(x0, f0[0], f0[1]); unpack2(x1, f0[2], f0[3]);
        unpack2(x2, f0[4], f0[5]); unpack2(x3, f0[6], f0[7]);
        unpack2(y0, f1[0], f1[1]); unpack2(y1, f1[2], f1[3]);
        unpack2(y2, f1[4], f1[5]); unpack2(y3, f1[6], f1[7]);
    } else {
        float k2[CC];
        #pragma unroll
        for (int c = 0; c < CC; c++) k2[c] = -0.5f * LOG2E * expf(-2.0f * sigma[c]);
        #pragma unroll
        for (int c = 0; c < CC; c++) { f0[c] = 0.0f; f1[c] = 0.0f; }
        for (int i = 0; i < NPW; i++) {
            int n = l0 + i;
            float x = s_abf2[n].x;
            float d0 = (x - t0) * (x - t0);
            float d1 = (x - t1) * (x - t1);
            const float* cf = (const float*)&s_cx[2 * n];
            #pragma unroll
            for (int c = 0; c < CC; c++) {
                f0[c] += ex2f(d0 * k2[c]) * cf[c];
                f1[c] += ex2f(d1 * k2[c]) * cf[c];
            }
        }
    }

    #pragma unroll
    for (int c = 0; c < CC; c++) {
        s_part[w][c][lane]      = f0[c];
        s_part[w][c][lane + 32] = f1[c];
    }
    __syncthreads();

    // in-CTA reduce over 8 warps -> 512-float partial for this slice
    {
        const int c   = tid >> 5;
        const int mm0 = tid & 31;
        float acc0 = 0.0f, acc1 = 0.0f;
        #pragma unroll
        for (int ww = 0; ww < NWARP; ww++) {
            acc0 += s_part[ww][c][mm0];
            acc1 += s_part[ww][c][mm0 + 32];
        }
        float* pp = g_part + ((size_t)grp * NSLC + ns) * (CC * MPB) + c * MPB;
        pp[mm0]      = acc0;
        pp[mm0 + 32] = acc1;
    }
}

// ---------------- reduce kernel: parallel slice-sum + normalize + GEMM ----------------
__global__ __launch_bounds__(RTPB)
void convdeepset_reduce(const float* __restrict__ ti,    // (B,M,1)
                        const float* __restrict__ sigma, // (8,)
                        const float* __restrict__ W,     // (64,8)
                        const float* __restrict__ bias,  // (64,)
                        float* __restrict__ out)         // (B,M,64)
{
    __shared__ float4 s_ld[NSLC][CC * MPB / 4];  // 8KB: one float4 per (slice, item)
    __shared__ float  s_v[CC][MPB];
    __shared__ float  s_dens[MPB];
    __shared__ float  s_Wt[CC][COUT];
    __shared__ float  s_bias[COUT];

    const int tid = threadIdx.x;
    const int blk = blockIdx.x;         // group = b*16 + mt
    const int b   = blk >> 4;
    const int mt  = blk & 15;
    const int mbase = mt * MPB;

    // phase A: one coalesced float4 L2 load per thread (512 thr = 4 slices x 128 items)
    {
        const int slice = tid >> 7;          // 0..3
        const int item  = tid & 127;         // (c, m4): c = item>>4, m4 = item&15
        const float4* src = (const float4*)(g_part + ((size_t)blk * NSLC + slice) * (CC * MPB));
        s_ld[slice][item] = src[item];
    }

    if (tid < CC * COUT) s_Wt[tid % CC][tid / CC] = W[tid];
    if (tid < COUT) s_bias[tid] = bias[tid];

    const float LOG2E = 1.4426950408889634f;
    float sg0 = sigma[0];
    bool uni = true;
    #pragma unroll
    for (int c = 1; c < CC; c++) uni &= (sigma[c] == sg0);
    const float k2u = -0.5f * LOG2E * expf(-2.0f * sg0);
    __syncthreads();

    // phase B: sum 4 slices (128 threads, float4 each), others idle briefly
    if (tid < CC * MPB / 4) {
        const int item = tid;
        const int c  = item >> 4;
        const int m4 = item & 15;
        float4 a = s_ld[0][item];
        float4 bq = s_ld[1][item];
        float4 cq = s_ld[2][item];
        float4 dq = s_ld[3][item];
        float4 s;
        s.x = (a.x + bq.x) + (cq.x + dq.x);
        s.y = (a.y + bq.y) + (cq.y + dq.y);
        s.z = (a.z + bq.z) + (cq.z + dq.z);
        s.w = (a.w + bq.w) + (cq.w + dq.w);
        s_v[c][m4 * 4 + 0] = s.x;
        s_v[c][m4 * 4 + 1] = s.y;
        s_v[c][m4 * 4 + 2] = s.z;
        s_v[c][m4 * 4 + 3] = s.w;
        if (c == 0) {
            s_dens[m4 * 4 + 0] = s.x;
            s_dens[m4 * 4 + 1] = s.y;
            s_dens[m4 * 4 + 2] = s.z;
            s_dens[m4 * 4 + 3] = s.w;
        }
    }
    __syncthreads();

    // phase C: normalize (512 threads = 8c x 64m)
    {
        const int c  = tid >> 6;
        const int mm = tid & 63;
        float tm = ti[(size_t)b * MMM + mbase + mm];
        float g  = uni ? ex2f(k2u * tm * tm) : 1.0f;
        float d0 = s_dens[mm] * g;                   // true density
        float inv = g / (d0 + 1e-8f);
        float val = s_v[c][mm];
        __syncthreads();                              // all reads done before overwrite
        s_v[c][mm] = (c == 0) ? d0 : val * inv;
    }
    __syncthreads();

    // phase D: (8 -> 64) GEMM + bias; thread = (mm = tid>>3, og = tid&7), 8 outputs
    {
        const int mm = tid >> 3;
        const int og = tid & 7;
        float v[CC];
        #pragma unroll
        for (int c = 0; c < CC; c++) v[c] = s_v[c][mm];

        float4 r0 = *(const float4*)&s_bias[og * 8];
        float4 r1 = *(const float4*)&s_bias[og * 8 + 4];
        #pragma unroll
        for (int c = 0; c < CC; c++) {
            float4 w0 = *(const float4*)&s_Wt[c][og * 8];
            float4 w1 = *(const float4*)&s_Wt[c][og * 8 + 4];
            r0.x = fmaf(v[c], w0.x, r0.x);
            r0.y = fmaf(v[c], w0.y, r0.y);
            r0.z = fmaf(v[c], w0.z, r0.z);
            r0.w = fmaf(v[c], w0.w, r0.w);
            r1.x = fmaf(v[c], w1.x, r1.x);
            r1.y = fmaf(v[c], w1.y, r1.y);
            r1.z = fmaf(v[c], w1.z, r1.z);
            r1.w = fmaf(v[c], w1.w, r1.w);
        }
        float4* outp = (float4*)(out + ((size_t)(b * MMM + mbase + mm)) * COUT + og * 8);
        outp[0] = r0;
        outp[1] = r1;
    }
}

extern "C" void kernel_launch(void* const* d_in, const int* in_sizes, int n_in,
                              void* d_out, int out_size) {
    const float* ci    = (const float*)d_in[0];
    const float* co    = (const float*)d_in[1];
    const float* ti    = (const float*)d_in[2];
    const float* sigma = (const float*)d_in[3];
    const float* W     = (const float*)d_in[4];
    const float* bias  = (const float*)d_in[5];
    float* out = (float*)d_out;

    convdeepset_main<<<NGRP * NSLC, TPB>>>(ci, co, ti, sigma);        // 1024 CTAs
    convdeepset_reduce<<<NGRP, RTPB>>>(ti, sigma, W, bias, out);      // 256 CTAs
}